// round 5
// baseline (speedup 1.0000x reference)
#include <cuda_runtime.h>

#define NN 100000
#define NP 100032
#define EI 800000
#define EE 400000
#define HH 128
#define GG 256
#define N_LAYERS 4
#define NTILES 1563        // NP/64
#define NB_NODE 3125       // 3125*32 = 100000
#define NB_CNT  4816       // covers EI+EE+GG*HH threads

// ---------------- scratch ----------------
__device__ float g_h [NP*HH];
__device__ float g_vp[NP*HH];
__device__ float g_vl[NP*HH];
__device__ float g_Ai[NP*HH];
__device__ float g_Ae[NP*HH];
__device__ float g_wint[EE];
__device__ int   g_degi[NN];   // zeroed by k_fc tail (zero-init on load)
__device__ int   g_dege[NN];
__device__ float g_sif[NP];
__device__ float g_bfi[NP];
__device__ float g_sef[NP];
__device__ float g_bfe[NP];
__device__ int   g_offi[NN+1];
__device__ int   g_offe[NN+1];
__device__ int   g_curi[NN];
__device__ int   g_cure[NN];
__device__ int   g_srci[EI];
__device__ float g_wi[EI];
__device__ int   g_srce[EE];
__device__ float g_we[EE];
__device__ int   g_parti[128];
__device__ int   g_parte[128];
__device__ int   g_basei[128];
__device__ int   g_basee[128];
__device__ int   g_scan_cnt;
__device__ int   g_scan_flag;
__device__ float g_pool[GG*HH];

__device__ __forceinline__ float silu_f(float x){ return x / (1.f + __expf(-x)); }
__device__ __forceinline__ unsigned long long dup2(float a){
    unsigned long long r; asm("mov.b64 %0, {%1, %1};" : "=l"(r) : "f"(a)); return r;
}
__device__ __forceinline__ void ffma2(unsigned long long& acc, unsigned long long a, unsigned long long b){
    asm("fma.rn.f32x2 %0, %1, %2, %0;" : "+l"(acc) : "l"(a), "l"(b));
}

// ---------------- 0: node init (lin_node+SiLU) + zero vp/vl + degree counts + inter w + pool zero ----------------
__global__ void k_init(const float* __restrict__ x, const float* __restrict__ W,
                       const float* __restrict__ b,
                       const int* __restrict__ ei, const int* __restrict__ ee,
                       const float* __restrict__ pos){
    int blk = blockIdx.x;
    if (blk < NB_NODE){
        __shared__ float Ws[35*HH];
        __shared__ float xs[32*35];
        int t = threadIdx.x;           // 256
        int n0 = blk*32;
        for (int i = t; i < 35*HH; i += 256) Ws[i] = W[i];
        for (int i = t; i < 32*35; i += 256){
            int node = i/35, k = i - node*35;
            xs[i] = x[(n0+node)*35 + k];
        }
        __syncthreads();
        int c = t & 127;
        int g = t >> 7;                // 0/1
        float bb = b[c];
        for (int idx = 0; idx < 16; idx++){
            int node = g*16 + idx;
            float acc = bb;
            #pragma unroll
            for (int k = 0; k < 35; k++) acc += xs[node*35+k]*Ws[k*HH+c];
            g_h[(n0+node)*HH + c] = silu_f(acc);
        }
        float4 z = make_float4(0.f,0.f,0.f,0.f);
        int base4 = n0*32;
        for (int i = t; i < 32*32; i += 256){
            ((float4*)g_vp)[base4+i] = z;
            ((float4*)g_vl)[base4+i] = z;
        }
    } else {
        int t = (blk - NB_NODE)*256 + threadIdx.x;
        if (t < EI){
            atomicAdd(&g_degi[ei[EI+t]], 1);
        } else if (t < EI+EE){
            int e = t - EI;
            int s = ee[e], d = ee[EE+e];
            float dx = pos[s*3+0]-pos[d*3+0];
            float dy = pos[s*3+1]-pos[d*3+1];
            float dz = pos[s*3+2]-pos[d*3+2];
            g_wint[e] = __expf(-(dx*dx+dy*dy+dz*dz));
            atomicAdd(&g_dege[d], 1);
        } else if (t < EI+EE+GG*HH){
            g_pool[t - EI - EE] = 0.f;
        }
    }
}

// ---------------- 1: merged scan (98 blocks, grid-spin handshake) ----------------
__global__ void k_scan(){
    __shared__ int s[1024];
    int b = blockIdx.x, b0 = b*1024;
    for (int pass = 0; pass < 2; pass++){
        const int* deg = pass ? g_dege : g_degi;
        int* off  = pass ? g_offe : g_offi;
        int* part = pass ? g_parte : g_parti;
        for (int i = threadIdx.x; i < 1024; i += 256){
            int n = b0 + i; s[i] = (n < NN) ? deg[n] : 0;
        }
        __syncthreads();
        for (int d = 1; d < 1024; d <<= 1){
            int t[4];
            #pragma unroll
            for (int j = 0; j < 4; j++){
                int i = threadIdx.x + j*256;
                t[j] = (i >= d) ? s[i-d] : 0;
            }
            __syncthreads();
            #pragma unroll
            for (int j = 0; j < 4; j++){
                int i = threadIdx.x + j*256;
                s[i] += t[j];
            }
            __syncthreads();
        }
        for (int i = threadIdx.x; i < 1024; i += 256){
            int n = b0 + i; if (n < NN) off[n+1] = s[i];
        }
        if (threadIdx.x == 0) atomicExch(&part[b], s[1023]);
        __syncthreads();
    }
    __threadfence();
    if (threadIdx.x == 0) atomicAdd(&g_scan_cnt, 1);

    if (b == 0){
        __shared__ int spi[128], spe[128];
        if (threadIdx.x == 0){
            int v; do { __nanosleep(64); v = atomicAdd(&g_scan_cnt, 0); } while (v < 98);
        }
        __syncthreads();
        int t = threadIdx.x;
        if (t < 128){
            spi[t] = (t < 98) ? atomicAdd(&g_parti[t], 0) : 0;
            spe[t] = (t < 98) ? atomicAdd(&g_parte[t], 0) : 0;
        }
        __syncthreads();
        for (int d = 1; d < 128; d <<= 1){
            int vi = 0, ve = 0;
            if (t < 128 && t >= d){ vi = spi[t-d]; ve = spe[t-d]; }
            __syncthreads();
            if (t < 128){ spi[t] += vi; spe[t] += ve; }
            __syncthreads();
        }
        if (t < 128){
            g_basei[t] = (t > 0) ? spi[t-1] : 0;
            g_basee[t] = (t > 0) ? spe[t-1] : 0;
        }
        __threadfence();
        __syncthreads();
        if (t == 0) atomicExch(&g_scan_flag, 1);
    }
    if (threadIdx.x == 0){
        int v; do { __nanosleep(64); v = atomicAdd(&g_scan_flag, 0); } while (!v);
    }
    __syncthreads();

    int basei = g_basei[b], basee = g_basee[b];
    for (int i = threadIdx.x; i < 1024; i += 256){
        int n = b0 + i;
        if (n >= NN) continue;
        int di = g_degi[n], de = g_dege[n];
        int oi = g_offi[n+1] + basei;
        int oe = g_offe[n+1] + basee;
        g_offi[n+1] = oi;
        g_offe[n+1] = oe;
        g_curi[n] = oi - di;
        g_cure[n] = oe - de;
        if (n == 0){ g_offi[0] = 0; g_offe[0] = 0; }
        float fdi = (float)di, fde = (float)de;
        float inv = 1.f/(fdi+1.f);
        g_sif[n] = inv;
        g_bfi[n] = fdi*inv;
        float L = logf(fde+1.f);
        g_sef[n] = L;
        g_bfe[n] = fde*L;
    }
}

// ---------------- 2: fill CSR (also resets scan handshake for next call) ----------------
__global__ void k_fill(const int* __restrict__ ei, const float* __restrict__ ea,
                       const int* __restrict__ ee){
    int t = blockIdx.x*blockDim.x + threadIdx.x;
    if (t == 0){ g_scan_cnt = 0; g_scan_flag = 0; }
    if (t < EI){
        int s = ei[t], d = ei[EI+t];
        int p = atomicAdd(&g_curi[d], 1);
        g_srci[p] = s; g_wi[p] = ea[t];
    } else if (t < EI+EE){
        int e = t - EI;
        int s = ee[e], d = ee[EE+e];
        int p = atomicAdd(&g_cure[d], 1);
        g_srce[p] = s; g_we[p] = g_wint[e];
    }
}

// ---------------- per layer: gather (warp per dst node, 4x unrolled edges) ----------------
__global__ void __launch_bounds__(256) k_gather(){
    int gw = (blockIdx.x*256 + threadIdx.x) >> 5;
    if (gw >= NN) return;
    int lane = threadIdx.x & 31;
    int c4 = lane*4;

    // intra
    {
        int a0 = g_offi[gw], a1 = g_offi[gw+1];
        float4 x0 = make_float4(0,0,0,0), x1 = x0, x2 = x0, x3 = x0;
        int j = a0;
        for (; j + 4 <= a1; j += 4){
            int s0 = __ldg(&g_srci[j+0]); float w0 = __ldg(&g_wi[j+0]);
            int s1 = __ldg(&g_srci[j+1]); float w1 = __ldg(&g_wi[j+1]);
            int s2 = __ldg(&g_srci[j+2]); float w2 = __ldg(&g_wi[j+2]);
            int s3 = __ldg(&g_srci[j+3]); float w3 = __ldg(&g_wi[j+3]);
            float4 h0 = *(const float4*)&g_h[s0*HH + c4];
            float4 h1 = *(const float4*)&g_h[s1*HH + c4];
            float4 h2 = *(const float4*)&g_h[s2*HH + c4];
            float4 h3 = *(const float4*)&g_h[s3*HH + c4];
            x0.x += w0*h0.x; x0.y += w0*h0.y; x0.z += w0*h0.z; x0.w += w0*h0.w;
            x1.x += w1*h1.x; x1.y += w1*h1.y; x1.z += w1*h1.z; x1.w += w1*h1.w;
            x2.x += w2*h2.x; x2.y += w2*h2.y; x2.z += w2*h2.z; x2.w += w2*h2.w;
            x3.x += w3*h3.x; x3.y += w3*h3.y; x3.z += w3*h3.z; x3.w += w3*h3.w;
        }
        for (; j < a1; j++){
            int s = __ldg(&g_srci[j]); float w = __ldg(&g_wi[j]);
            float4 hv = *(const float4*)&g_h[s*HH + c4];
            x0.x += w*hv.x; x0.y += w*hv.y; x0.z += w*hv.z; x0.w += w*hv.w;
        }
        float sc = g_sif[gw];
        *(float4*)&g_Ai[gw*HH + c4] = make_float4(
            (x0.x+x1.x+x2.x+x3.x)*sc, (x0.y+x1.y+x2.y+x3.y)*sc,
            (x0.z+x1.z+x2.z+x3.z)*sc, (x0.w+x1.w+x2.w+x3.w)*sc);
    }
    // inter
    {
        int a0 = g_offe[gw], a1 = g_offe[gw+1];
        float4 x0 = make_float4(0,0,0,0), x1 = x0, x2 = x0, x3 = x0;
        int j = a0;
        for (; j + 4 <= a1; j += 4){
            int s0 = __ldg(&g_srce[j+0]); float w0 = __ldg(&g_we[j+0]);
            int s1 = __ldg(&g_srce[j+1]); float w1 = __ldg(&g_we[j+1]);
            int s2 = __ldg(&g_srce[j+2]); float w2 = __ldg(&g_we[j+2]);
            int s3 = __ldg(&g_srce[j+3]); float w3 = __ldg(&g_we[j+3]);
            float4 h0 = *(const float4*)&g_h[s0*HH + c4];
            float4 h1 = *(const float4*)&g_h[s1*HH + c4];
            float4 h2 = *(const float4*)&g_h[s2*HH + c4];
            float4 h3 = *(const float4*)&g_h[s3*HH + c4];
            x0.x += w0*h0.x; x0.y += w0*h0.y; x0.z += w0*h0.z; x0.w += w0*h0.w;
            x1.x += w1*h1.x; x1.y += w1*h1.y; x1.z += w1*h1.z; x1.w += w1*h1.w;
            x2.x += w2*h2.x; x2.y += w2*h2.y; x2.z += w2*h2.z; x2.w += w2*h2.w;
            x3.x += w3*h3.x; x3.y += w3*h3.y; x3.z += w3*h3.z; x3.w += w3*h3.w;
        }
        for (; j < a1; j++){
            int s = __ldg(&g_srce[j]); float w = __ldg(&g_we[j]);
            float4 hv = *(const float4*)&g_h[s*HH + c4];
            x0.x += w*hv.x; x0.y += w*hv.y; x0.z += w*hv.z; x0.w += w*hv.w;
        }
        float sc = g_sef[gw];
        *(float4*)&g_Ae[gw*HH + c4] = make_float4(
            (x0.x+x1.x+x2.x+x3.x)*sc, (x0.y+x1.y+x2.y+x3.y)*sc,
            (x0.z+x1.z+x2.z+x3.z)*sc, (x0.w+x1.w+x2.w+x3.w)*sc);
    }
}

// ---------------- per layer: dual GEMM + bias + SiLU + state update ----------------
#define AST 132
#define SMEM_LAYER ((128*256 + 2*64*AST)*sizeof(float))   // 198656 B

__global__ void __launch_bounds__(256,1) k_layer(
        const float* __restrict__ Wi, const float* __restrict__ We,
        const float* __restrict__ bi, const float* __restrict__ be)
{
    extern __shared__ float sm[];
    float* ws  = sm;                 // [128][256]
    float* asi = ws  + 128*256;      // [64][AST], reused as sv_p
    float* ase = asi + 64*AST;       // [64][AST], reused as sv_l
    int tid = threadIdx.x;
    int cg = tid & 31, rg = tid >> 5;
    int c4 = cg*4;

    for (int i = tid; i < 8192; i += 256){
        int k = i >> 6;
        int c = (i & 63)*4;
        float4 v = (c < 128) ? *(const float4*)&Wi[k*128 + c]
                             : *(const float4*)&We[k*128 + (c-128)];
        *(float4*)&ws[k*256 + c] = v;
    }
    float4 bvi = *(const float4*)&bi[c4];
    float4 bve = *(const float4*)&be[c4];

    for (int tile = blockIdx.x; tile < NTILES; tile += gridDim.x){
        int n0 = tile*64;

        for (int i = tid; i < 2048; i += 256){
            int row = i >> 5, kc = (i & 31)*4;
            int goff = (n0+row)*HH + kc;
            *(float4*)&asi[row*AST + kc] = *(const float4*)&g_Ai[goff];
            *(float4*)&ase[row*AST + kc] = *(const float4*)&g_Ae[goff];
        }
        __syncthreads();

        unsigned long long acci[8][2], acce[8][2];
        #pragma unroll
        for (int r = 0; r < 8; r++){ acci[r][0]=0ull; acci[r][1]=0ull; acce[r][0]=0ull; acce[r][1]=0ull; }

        const float* arow_i = asi + rg*8*AST;
        const float* arow_e = ase + rg*8*AST;

        #pragma unroll 2
        for (int k0 = 0; k0 < 128; k0 += 4){
            float4 a4[8];
            #pragma unroll
            for (int r = 0; r < 8; r++) a4[r] = *(const float4*)&arow_i[r*AST + k0];
            #pragma unroll
            for (int kk = 0; kk < 4; kk++){
                ulonglong2 w2 = *(const ulonglong2*)&ws[(k0+kk)*256 + c4];
                #pragma unroll
                for (int r = 0; r < 8; r++){
                    float a = (kk==0)?a4[r].x:(kk==1)?a4[r].y:(kk==2)?a4[r].z:a4[r].w;
                    unsigned long long aa = dup2(a);
                    ffma2(acci[r][0], aa, w2.x);
                    ffma2(acci[r][1], aa, w2.y);
                }
            }
        }
        #pragma unroll 2
        for (int k0 = 0; k0 < 128; k0 += 4){
            float4 a4[8];
            #pragma unroll
            for (int r = 0; r < 8; r++) a4[r] = *(const float4*)&arow_e[r*AST + k0];
            #pragma unroll
            for (int kk = 0; kk < 4; kk++){
                ulonglong2 w2 = *(const ulonglong2*)&ws[(k0+kk)*256 + 128 + c4];
                #pragma unroll
                for (int r = 0; r < 8; r++){
                    float a = (kk==0)?a4[r].x:(kk==1)?a4[r].y:(kk==2)?a4[r].z:a4[r].w;
                    unsigned long long aa = dup2(a);
                    ffma2(acce[r][0], aa, w2.x);
                    ffma2(acce[r][1], aa, w2.y);
                }
            }
        }

        #pragma unroll
        for (int r = 0; r < 8; r++){
            int nl = rg*8 + r;
            int n  = n0 + nl;
            float bf   = g_bfi[n];
            float bfe_ = g_bfe[n];
            float2 p0 = *(float2*)&acci[r][0];
            float2 p1 = *(float2*)&acci[r][1];
            float4 vo = *(const float4*)&g_vp[n*HH + c4];
            float4 v;
            v.x = silu_f(p0.x + bvi.x*bf + vo.x);
            v.y = silu_f(p0.y + bvi.y*bf + vo.y);
            v.z = silu_f(p1.x + bvi.z*bf + vo.z);
            v.w = silu_f(p1.y + bvi.w*bf + vo.w);
            *(float4*)&g_vp[n*HH + c4] = v;
            *(float4*)&asi[nl*AST + c4] = v;

            float2 q0 = *(float2*)&acce[r][0];
            float2 q1 = *(float2*)&acce[r][1];
            float4 uo = *(const float4*)&g_vl[n*HH + c4];
            float4 u;
            u.x = silu_f(q0.x + bve.x*bfe_ + uo.x);
            u.y = silu_f(q0.y + bve.y*bfe_ + uo.y);
            u.z = silu_f(q1.x + bve.z*bfe_ + uo.z);
            u.w = silu_f(q1.y + bve.w*bfe_ + uo.w);
            *(float4*)&g_vl[n*HH + c4] = u;
            *(float4*)&ase[nl*AST + c4] = u;
        }
        __syncthreads();

        for (int i = tid; i < 2048; i += 256){
            int row = i >> 5, kc = (i & 31)*4;
            int goff = (n0+row)*HH + kc;
            float4 hv = *(const float4*)&g_h[goff];
            float4 p  = *(const float4*)&asi[row*AST + kc];
            float4 q  = *(const float4*)&ase[row*AST + kc];
            hv.x += p.x+q.x; hv.y += p.y+q.y; hv.z += p.z+q.z; hv.w += p.w+q.w;
            *(float4*)&g_h[goff] = hv;
        }
        __syncthreads();
    }
}

// ---------------- pooling ----------------
__global__ void k_pool(const int* __restrict__ batch){
    __shared__ int sb[512];
    int c = threadIdx.x;
    int n0 = blockIdx.x*512;
    if (n0 >= NN) return;
    int nend = min(n0+512, NN);
    int cnt = nend - n0;
    for (int i = c; i < cnt; i += 128) sb[i] = batch[n0+i];
    __syncthreads();
    int cur = sb[0];
    float acc = 0.f;
    for (int k = 0; k < cnt; k++){
        int b = sb[k];
        if (b != cur){
            atomicAdd(&g_pool[cur*HH+c], acc);
            acc = 0.f; cur = b;
        }
        acc += g_h[(n0+k)*HH+c];
    }
    atomicAdd(&g_pool[cur*HH+c], acc);
}

// ---------------- FC head (+ degree re-zero for next call) ----------------
__global__ void k_fc(const float* __restrict__ fcW, const float* __restrict__ fcb,
                     const float* __restrict__ gam, const float* __restrict__ bet,
                     const float* __restrict__ oW,  const float* __restrict__ ob,
                     float* __restrict__ out){
    int g = blockIdx.x, c = threadIdx.x;
    __shared__ float s[HH];
    __shared__ float red[HH];
    s[c] = g_pool[g*HH + c];
    for (int i = g*128 + c; i < NN; i += GG*128){ g_degi[i] = 0; g_dege[i] = 0; }
    __syncthreads();
    const float bns = rsqrtf(1.f + 1e-5f);
    for (int j = 0; j < 3; j++){
        const float* W = fcW + j*HH*HH;
        float acc = fcb[j*HH+c];
        #pragma unroll 8
        for (int k = 0; k < HH; k++) acc += s[k]*W[k*HH+c];
        acc = acc > 0.f ? acc : 0.01f*acc;
        acc = acc*bns*gam[j*HH+c] + bet[j*HH+c];
        __syncthreads();
        s[c] = acc;
        __syncthreads();
    }
    red[c] = s[c]*oW[c];
    __syncthreads();
    for (int o = 64; o > 0; o >>= 1){
        if (c < o) red[c] += red[c+o];
        __syncthreads();
    }
    if (c == 0) out[g] = red[0] + ob[0];
}

// ---------------- host ----------------
extern "C" void kernel_launch(void* const* d_in, const int* in_sizes, int n_in,
                              void* d_out, int out_size){
    const float* x    = (const float*)d_in[0];
    const int*   ei   = (const int*)  d_in[1];
    const int*   ee   = (const int*)  d_in[2];
    const float* pos  = (const float*)d_in[3];
    const float* ea   = (const float*)d_in[4];
    const int*   batch= (const int*)  d_in[5];
    const float* lnW  = (const float*)d_in[6];
    const float* lnb  = (const float*)d_in[7];
    const float* Wi   = (const float*)d_in[8];
    const float* bi   = (const float*)d_in[9];
    const float* We   = (const float*)d_in[10];
    const float* be   = (const float*)d_in[11];
    const float* fcW  = (const float*)d_in[12];
    const float* fcb  = (const float*)d_in[13];
    const float* gam  = (const float*)d_in[14];
    const float* bet  = (const float*)d_in[15];
    const float* oW   = (const float*)d_in[16];
    const float* ob   = (const float*)d_in[17];
    float* out = (float*)d_out;

    cudaFuncSetAttribute(k_layer, cudaFuncAttributeMaxDynamicSharedMemorySize, (int)SMEM_LAYER);

    k_init<<<NB_NODE + NB_CNT, 256>>>(x, lnW, lnb, ei, ee, pos);  // 0
    k_scan<<<98, 256>>>();                                        // 1
    k_fill<<<(EI+EE+255)/256, 256>>>(ei, ea, ee);                 // 2

    for (int l = 0; l < N_LAYERS; l++){
        k_gather<<<(NN*32+255)/256, 256>>>();                     // 3 (ncu capture), 5, 7, 9
        k_layer<<<148, 256, SMEM_LAYER>>>(Wi + l*HH*HH, We + l*HH*HH,
                                          bi + l*HH,    be + l*HH); // 4, 6, 8, 10
    }

    k_pool<<<(NN+511)/512, 128>>>(batch);                         // 11
    k_fc<<<GG, 128>>>(fcW, fcb, gam, bet, oW, ob, out);           // 12
}

// round 6
// speedup vs baseline: 1.3765x; 1.3765x over previous
#include <cuda_runtime.h>

#define NN 100000
#define NP 100032
#define EI 800000
#define EE 400000
#define HH 128
#define GG 256
#define N_LAYERS 4
#define NTILES 1563        // NP/64
#define NB_NODE 3125       // 3125*32 = 100000
#define NB_CNT  4816       // covers EI+EE+GG*HH threads
#define PREP_B 98
#define PREP_T 256
#define PREP_NT (PREP_B*PREP_T)

// ---------------- scratch ----------------
__device__ float g_h [NP*HH];
__device__ float g_vp[NP*HH];
__device__ float g_vl[NP*HH];
__device__ float g_Ai[NP*HH];
__device__ float g_Ae[NP*HH];
__device__ float g_wint[EE];
__device__ int   g_degi[NN];   // zeroed by k_fc tail (zero-init on load)
__device__ int   g_dege[NN];
__device__ float g_sif[NP];
__device__ float g_bfi[NP];
__device__ float g_sef[NP];
__device__ float g_bfe[NP];
__device__ int   g_offi[NN+1];
__device__ int   g_offe[NN+1];
__device__ int   g_curi[NN];
__device__ int   g_cure[NN];
__device__ int   g_srci[EI];
__device__ float g_wi[EI];
__device__ int   g_srce[EE];
__device__ float g_we[EE];
__device__ int   g_parti[128];
__device__ int   g_parte[128];
__device__ int   g_cnt1;
__device__ int   g_cnt2;
__device__ float g_pool[GG*HH];

__device__ __forceinline__ float silu_f(float x){ return x / (1.f + __expf(-x)); }
__device__ __forceinline__ unsigned long long dup2(float a){
    unsigned long long r; asm("mov.b64 %0, {%1, %1};" : "=l"(r) : "f"(a)); return r;
}
__device__ __forceinline__ void ffma2(unsigned long long& acc, unsigned long long a, unsigned long long b){
    asm("fma.rn.f32x2 %0, %1, %2, %0;" : "+l"(acc) : "l"(a), "l"(b));
}

// ---------------- 1: node init + degree counts + inter weight + pool zero + counter reset ----------------
__global__ void k_init(const float* __restrict__ x, const float* __restrict__ W,
                       const float* __restrict__ b,
                       const int* __restrict__ ei, const int* __restrict__ ee,
                       const float* __restrict__ pos){
    int blk = blockIdx.x;
    if (blk == 0 && threadIdx.x == 0){ g_cnt1 = 0; g_cnt2 = 0; }
    if (blk < NB_NODE){
        __shared__ float Ws[35*HH];
        __shared__ float xs[32*35];
        int t = threadIdx.x;           // 256
        int n0 = blk*32;
        for (int i = t; i < 35*HH; i += 256) Ws[i] = W[i];
        for (int i = t; i < 32*35; i += 256){
            int node = i/35, k = i - node*35;
            xs[i] = x[(n0+node)*35 + k];
        }
        __syncthreads();
        int c = t & 127;
        int g = t >> 7;                // 0/1
        float bb = b[c];
        for (int idx = 0; idx < 16; idx++){
            int node = g*16 + idx;
            float acc = bb;
            #pragma unroll
            for (int k = 0; k < 35; k++) acc += xs[node*35+k]*Ws[k*HH+c];
            g_h[(n0+node)*HH + c] = silu_f(acc);
        }
        float4 z = make_float4(0.f,0.f,0.f,0.f);
        int base4 = n0*32;
        for (int i = t; i < 32*32; i += 256){
            ((float4*)g_vp)[base4+i] = z;
            ((float4*)g_vl)[base4+i] = z;
        }
    } else {
        int t = (blk - NB_NODE)*256 + threadIdx.x;
        if (t < EI){
            atomicAdd(&g_degi[ei[EI+t]], 1);
        } else if (t < EI+EE){
            int e = t - EI;
            int s = ee[e], d = ee[EE+e];
            float dx = pos[s*3+0]-pos[d*3+0];
            float dy = pos[s*3+1]-pos[d*3+1];
            float dz = pos[s*3+2]-pos[d*3+2];
            g_wint[e] = __expf(-(dx*dx+dy*dy+dz*dz));
            atomicAdd(&g_dege[d], 1);
        } else if (t < EI+EE+GG*HH){
            g_pool[t - EI - EE] = 0.f;
        }
    }
}

// ---------------- 2: scan + offsets/cursors/factors + CSR fill (98 co-resident blocks) ----------------
__global__ void __launch_bounds__(PREP_T) k_prep(const int* __restrict__ ei,
                                                 const float* __restrict__ ea,
                                                 const int* __restrict__ ee){
    __shared__ int s[1024];
    __shared__ int spi[128], spe[128];
    int b = blockIdx.x, b0 = b*1024, t = threadIdx.x;

    // per-chunk inclusive scan (both degree arrays)
    for (int pass = 0; pass < 2; pass++){
        const int* deg = pass ? g_dege : g_degi;
        int* off  = pass ? g_offe : g_offi;
        int* part = pass ? g_parte : g_parti;
        for (int i = t; i < 1024; i += 256){
            int n = b0 + i; s[i] = (n < NN) ? deg[n] : 0;
        }
        __syncthreads();
        for (int d = 1; d < 1024; d <<= 1){
            int tmp[4];
            #pragma unroll
            for (int j = 0; j < 4; j++){
                int i = t + j*256;
                tmp[j] = (i >= d) ? s[i-d] : 0;
            }
            __syncthreads();
            #pragma unroll
            for (int j = 0; j < 4; j++) s[t + j*256] += tmp[j];
            __syncthreads();
        }
        for (int i = t; i < 1024; i += 256){
            int n = b0 + i; if (n < NN) off[n+1] = s[i];
        }
        if (t == 0) atomicExch(&part[b], s[1023]);
        __syncthreads();
    }
    __threadfence();
    if (t == 0){
        atomicAdd(&g_cnt1, 1);
        int v; do { __nanosleep(128); v = atomicAdd(&g_cnt1, 0); } while (v < PREP_B);
    }
    __syncthreads();

    // every block redundantly scans the 98 partials (cheap, avoids a second round-trip)
    if (t < 128){
        spi[t] = (t < PREP_B) ? atomicAdd(&g_parti[t], 0) : 0;
        spe[t] = (t < PREP_B) ? atomicAdd(&g_parte[t], 0) : 0;
    }
    __syncthreads();
    for (int d = 1; d < 128; d <<= 1){
        int vi = 0, ve = 0;
        if (t < 128 && t >= d){ vi = spi[t-d]; ve = spe[t-d]; }
        __syncthreads();
        if (t < 128){ spi[t] += vi; spe[t] += ve; }
        __syncthreads();
    }
    int basei = (b > 0) ? spi[b-1] : 0;
    int basee = (b > 0) ? spe[b-1] : 0;

    for (int i = t; i < 1024; i += 256){
        int n = b0 + i;
        if (n >= NN) continue;
        int di = g_degi[n], de = g_dege[n];
        int oi = g_offi[n+1] + basei;
        int oe = g_offe[n+1] + basee;
        g_offi[n+1] = oi;
        g_offe[n+1] = oe;
        g_curi[n] = oi - di;
        g_cure[n] = oe - de;
        if (n == 0){ g_offi[0] = 0; g_offe[0] = 0; }
        float fdi = (float)di, fde = (float)de;
        float inv = 1.f/(fdi+1.f);
        g_sif[n] = inv;
        g_bfi[n] = fdi*inv;
        float L = logf(fde+1.f);
        g_sef[n] = L;
        g_bfe[n] = fde*L;
    }
    __threadfence();
    __syncthreads();
    if (t == 0){
        atomicAdd(&g_cnt2, 1);
        int v; do { __nanosleep(128); v = atomicAdd(&g_cnt2, 0); } while (v < PREP_B);
    }
    __syncthreads();

    // CSR fill (cursor increments are atomic RMW -> always see latest)
    for (int e = b*PREP_T + t; e < EI; e += PREP_NT){
        int s_ = ei[e], d = ei[EI+e];
        int p = atomicAdd(&g_curi[d], 1);
        g_srci[p] = s_; g_wi[p] = ea[e];
    }
    for (int e = b*PREP_T + t; e < EE; e += PREP_NT){
        int s_ = ee[e], d = ee[EE+e];
        int p = atomicAdd(&g_cure[d], 1);
        g_srce[p] = s_; g_we[p] = g_wint[e];
    }
}

// ---------------- per layer: gather (warp per dst node, 4x unrolled edges) ----------------
__global__ void __launch_bounds__(256) k_gather(){
    int gw = (blockIdx.x*256 + threadIdx.x) >> 5;
    if (gw >= NN) return;
    int lane = threadIdx.x & 31;
    int c4 = lane*4;

    // intra
    {
        int a0 = g_offi[gw], a1 = g_offi[gw+1];
        float4 x0 = make_float4(0,0,0,0), x1 = x0, x2 = x0, x3 = x0;
        int j = a0;
        for (; j + 4 <= a1; j += 4){
            int s0 = __ldg(&g_srci[j+0]); float w0 = __ldg(&g_wi[j+0]);
            int s1 = __ldg(&g_srci[j+1]); float w1 = __ldg(&g_wi[j+1]);
            int s2 = __ldg(&g_srci[j+2]); float w2 = __ldg(&g_wi[j+2]);
            int s3 = __ldg(&g_srci[j+3]); float w3 = __ldg(&g_wi[j+3]);
            float4 h0 = *(const float4*)&g_h[s0*HH + c4];
            float4 h1 = *(const float4*)&g_h[s1*HH + c4];
            float4 h2 = *(const float4*)&g_h[s2*HH + c4];
            float4 h3 = *(const float4*)&g_h[s3*HH + c4];
            x0.x += w0*h0.x; x0.y += w0*h0.y; x0.z += w0*h0.z; x0.w += w0*h0.w;
            x1.x += w1*h1.x; x1.y += w1*h1.y; x1.z += w1*h1.z; x1.w += w1*h1.w;
            x2.x += w2*h2.x; x2.y += w2*h2.y; x2.z += w2*h2.z; x2.w += w2*h2.w;
            x3.x += w3*h3.x; x3.y += w3*h3.y; x3.z += w3*h3.z; x3.w += w3*h3.w;
        }
        for (; j < a1; j++){
            int s = __ldg(&g_srci[j]); float w = __ldg(&g_wi[j]);
            float4 hv = *(const float4*)&g_h[s*HH + c4];
            x0.x += w*hv.x; x0.y += w*hv.y; x0.z += w*hv.z; x0.w += w*hv.w;
        }
        float sc = g_sif[gw];
        *(float4*)&g_Ai[gw*HH + c4] = make_float4(
            (x0.x+x1.x+x2.x+x3.x)*sc, (x0.y+x1.y+x2.y+x3.y)*sc,
            (x0.z+x1.z+x2.z+x3.z)*sc, (x0.w+x1.w+x2.w+x3.w)*sc);
    }
    // inter
    {
        int a0 = g_offe[gw], a1 = g_offe[gw+1];
        float4 x0 = make_float4(0,0,0,0), x1 = x0, x2 = x0, x3 = x0;
        int j = a0;
        for (; j + 4 <= a1; j += 4){
            int s0 = __ldg(&g_srce[j+0]); float w0 = __ldg(&g_we[j+0]);
            int s1 = __ldg(&g_srce[j+1]); float w1 = __ldg(&g_we[j+1]);
            int s2 = __ldg(&g_srce[j+2]); float w2 = __ldg(&g_we[j+2]);
            int s3 = __ldg(&g_srce[j+3]); float w3 = __ldg(&g_we[j+3]);
            float4 h0 = *(const float4*)&g_h[s0*HH + c4];
            float4 h1 = *(const float4*)&g_h[s1*HH + c4];
            float4 h2 = *(const float4*)&g_h[s2*HH + c4];
            float4 h3 = *(const float4*)&g_h[s3*HH + c4];
            x0.x += w0*h0.x; x0.y += w0*h0.y; x0.z += w0*h0.z; x0.w += w0*h0.w;
            x1.x += w1*h1.x; x1.y += w1*h1.y; x1.z += w1*h1.z; x1.w += w1*h1.w;
            x2.x += w2*h2.x; x2.y += w2*h2.y; x2.z += w2*h2.z; x2.w += w2*h2.w;
            x3.x += w3*h3.x; x3.y += w3*h3.y; x3.z += w3*h3.z; x3.w += w3*h3.w;
        }
        for (; j < a1; j++){
            int s = __ldg(&g_srce[j]); float w = __ldg(&g_we[j]);
            float4 hv = *(const float4*)&g_h[s*HH + c4];
            x0.x += w*hv.x; x0.y += w*hv.y; x0.z += w*hv.z; x0.w += w*hv.w;
        }
        float sc = g_sef[gw];
        *(float4*)&g_Ae[gw*HH + c4] = make_float4(
            (x0.x+x1.x+x2.x+x3.x)*sc, (x0.y+x1.y+x2.y+x3.y)*sc,
            (x0.z+x1.z+x2.z+x3.z)*sc, (x0.w+x1.w+x2.w+x3.w)*sc);
    }
}

// ---------------- per layer: dual GEMM + bias + SiLU + state update ----------------
#define AST 132
#define SMEM_LAYER ((128*256 + 2*64*AST)*sizeof(float))   // 198656 B

__global__ void __launch_bounds__(256,1) k_layer(
        const float* __restrict__ Wi, const float* __restrict__ We,
        const float* __restrict__ bi, const float* __restrict__ be)
{
    extern __shared__ float sm[];
    float* ws  = sm;                 // [128][256]
    float* asi = ws  + 128*256;      // [64][AST], reused as sv_p
    float* ase = asi + 64*AST;       // [64][AST], reused as sv_l
    int tid = threadIdx.x;
    int cg = tid & 31, rg = tid >> 5;
    int c4 = cg*4;

    for (int i = tid; i < 8192; i += 256){
        int k = i >> 6;
        int c = (i & 63)*4;
        float4 v = (c < 128) ? *(const float4*)&Wi[k*128 + c]
                             : *(const float4*)&We[k*128 + (c-128)];
        *(float4*)&ws[k*256 + c] = v;
    }
    float4 bvi = *(const float4*)&bi[c4];
    float4 bve = *(const float4*)&be[c4];

    for (int tile = blockIdx.x; tile < NTILES; tile += gridDim.x){
        int n0 = tile*64;

        for (int i = tid; i < 2048; i += 256){
            int row = i >> 5, kc = (i & 31)*4;
            int goff = (n0+row)*HH + kc;
            *(float4*)&asi[row*AST + kc] = *(const float4*)&g_Ai[goff];
            *(float4*)&ase[row*AST + kc] = *(const float4*)&g_Ae[goff];
        }
        __syncthreads();

        unsigned long long acci[8][2], acce[8][2];
        #pragma unroll
        for (int r = 0; r < 8; r++){ acci[r][0]=0ull; acci[r][1]=0ull; acce[r][0]=0ull; acce[r][1]=0ull; }

        const float* arow_i = asi + rg*8*AST;
        const float* arow_e = ase + rg*8*AST;

        #pragma unroll 2
        for (int k0 = 0; k0 < 128; k0 += 4){
            float4 a4[8];
            #pragma unroll
            for (int r = 0; r < 8; r++) a4[r] = *(const float4*)&arow_i[r*AST + k0];
            #pragma unroll
            for (int kk = 0; kk < 4; kk++){
                ulonglong2 w2 = *(const ulonglong2*)&ws[(k0+kk)*256 + c4];
                #pragma unroll
                for (int r = 0; r < 8; r++){
                    float a = (kk==0)?a4[r].x:(kk==1)?a4[r].y:(kk==2)?a4[r].z:a4[r].w;
                    unsigned long long aa = dup2(a);
                    ffma2(acci[r][0], aa, w2.x);
                    ffma2(acci[r][1], aa, w2.y);
                }
            }
        }
        #pragma unroll 2
        for (int k0 = 0; k0 < 128; k0 += 4){
            float4 a4[8];
            #pragma unroll
            for (int r = 0; r < 8; r++) a4[r] = *(const float4*)&arow_e[r*AST + k0];
            #pragma unroll
            for (int kk = 0; kk < 4; kk++){
                ulonglong2 w2 = *(const ulonglong2*)&ws[(k0+kk)*256 + 128 + c4];
                #pragma unroll
                for (int r = 0; r < 8; r++){
                    float a = (kk==0)?a4[r].x:(kk==1)?a4[r].y:(kk==2)?a4[r].z:a4[r].w;
                    unsigned long long aa = dup2(a);
                    ffma2(acce[r][0], aa, w2.x);
                    ffma2(acce[r][1], aa, w2.y);
                }
            }
        }

        #pragma unroll
        for (int r = 0; r < 8; r++){
            int nl = rg*8 + r;
            int n  = n0 + nl;
            float bf   = g_bfi[n];
            float bfe_ = g_bfe[n];
            float2 p0 = *(float2*)&acci[r][0];
            float2 p1 = *(float2*)&acci[r][1];
            float4 vo = *(const float4*)&g_vp[n*HH + c4];
            float4 v;
            v.x = silu_f(p0.x + bvi.x*bf + vo.x);
            v.y = silu_f(p0.y + bvi.y*bf + vo.y);
            v.z = silu_f(p1.x + bvi.z*bf + vo.z);
            v.w = silu_f(p1.y + bvi.w*bf + vo.w);
            *(float4*)&g_vp[n*HH + c4] = v;
            *(float4*)&asi[nl*AST + c4] = v;

            float2 q0 = *(float2*)&acce[r][0];
            float2 q1 = *(float2*)&acce[r][1];
            float4 uo = *(const float4*)&g_vl[n*HH + c4];
            float4 u;
            u.x = silu_f(q0.x + bve.x*bfe_ + uo.x);
            u.y = silu_f(q0.y + bve.y*bfe_ + uo.y);
            u.z = silu_f(q1.x + bve.z*bfe_ + uo.z);
            u.w = silu_f(q1.y + bve.w*bfe_ + uo.w);
            *(float4*)&g_vl[n*HH + c4] = u;
            *(float4*)&ase[nl*AST + c4] = u;
        }
        __syncthreads();

        for (int i = tid; i < 2048; i += 256){
            int row = i >> 5, kc = (i & 31)*4;
            int goff = (n0+row)*HH + kc;
            float4 hv = *(const float4*)&g_h[goff];
            float4 p  = *(const float4*)&asi[row*AST + kc];
            float4 q  = *(const float4*)&ase[row*AST + kc];
            hv.x += p.x+q.x; hv.y += p.y+q.y; hv.z += p.z+q.z; hv.w += p.w+q.w;
            *(float4*)&g_h[goff] = hv;
        }
        __syncthreads();
    }
}

// ---------------- pooling ----------------
__global__ void k_pool(const int* __restrict__ batch){
    __shared__ int sb[512];
    int c = threadIdx.x;
    int n0 = blockIdx.x*512;
    if (n0 >= NN) return;
    int nend = min(n0+512, NN);
    int cnt = nend - n0;
    for (int i = c; i < cnt; i += 128) sb[i] = batch[n0+i];
    __syncthreads();
    int cur = sb[0];
    float acc = 0.f;
    for (int k = 0; k < cnt; k++){
        int b = sb[k];
        if (b != cur){
            atomicAdd(&g_pool[cur*HH+c], acc);
            acc = 0.f; cur = b;
        }
        acc += g_h[(n0+k)*HH+c];
    }
    atomicAdd(&g_pool[cur*HH+c], acc);
}

// ---------------- FC head (+ degree re-zero for next call) ----------------
__global__ void k_fc(const float* __restrict__ fcW, const float* __restrict__ fcb,
                     const float* __restrict__ gam, const float* __restrict__ bet,
                     const float* __restrict__ oW,  const float* __restrict__ ob,
                     float* __restrict__ out){
    int g = blockIdx.x, c = threadIdx.x;
    __shared__ float s[HH];
    __shared__ float red[HH];
    s[c] = g_pool[g*HH + c];
    for (int i = g*128 + c; i < NN; i += GG*128){ g_degi[i] = 0; g_dege[i] = 0; }
    __syncthreads();
    const float bns = rsqrtf(1.f + 1e-5f);
    for (int j = 0; j < 3; j++){
        const float* W = fcW + j*HH*HH;
        float acc = fcb[j*HH+c];
        #pragma unroll 8
        for (int k = 0; k < HH; k++) acc += s[k]*W[k*HH+c];
        acc = acc > 0.f ? acc : 0.01f*acc;
        acc = acc*bns*gam[j*HH+c] + bet[j*HH+c];
        __syncthreads();
        s[c] = acc;
        __syncthreads();
    }
    red[c] = s[c]*oW[c];
    __syncthreads();
    for (int o = 64; o > 0; o >>= 1){
        if (c < o) red[c] += red[c+o];
        __syncthreads();
    }
    if (c == 0) out[g] = red[0] + ob[0];
}

// ---------------- host ----------------
extern "C" void kernel_launch(void* const* d_in, const int* in_sizes, int n_in,
                              void* d_out, int out_size){
    const float* x    = (const float*)d_in[0];
    const int*   ei   = (const int*)  d_in[1];
    const int*   ee   = (const int*)  d_in[2];
    const float* pos  = (const float*)d_in[3];
    const float* ea   = (const float*)d_in[4];
    const int*   batch= (const int*)  d_in[5];
    const float* lnW  = (const float*)d_in[6];
    const float* lnb  = (const float*)d_in[7];
    const float* Wi   = (const float*)d_in[8];
    const float* bi   = (const float*)d_in[9];
    const float* We   = (const float*)d_in[10];
    const float* be   = (const float*)d_in[11];
    const float* fcW  = (const float*)d_in[12];
    const float* fcb  = (const float*)d_in[13];
    const float* gam  = (const float*)d_in[14];
    const float* bet  = (const float*)d_in[15];
    const float* oW   = (const float*)d_in[16];
    const float* ob   = (const float*)d_in[17];
    float* out = (float*)d_out;

    cudaFuncSetAttribute(k_layer, cudaFuncAttributeMaxDynamicSharedMemorySize, (int)SMEM_LAYER);

    k_init<<<NB_NODE + NB_CNT, 256>>>(x, lnW, lnb, ei, ee, pos);  // launch 1
    k_prep<<<PREP_B, PREP_T>>>(ei, ea, ee);                       // launch 2

    for (int l = 0; l < N_LAYERS; l++){
        k_gather<<<(NN*32+255)/256, 256>>>();                     // launch 3,5,7,9
        k_layer<<<148, 256, SMEM_LAYER>>>(Wi + l*HH*HH, We + l*HH*HH,
                                          bi + l*HH,    be + l*HH); // launch 4 (ncu capture),6,8,10
    }

    k_pool<<<(NN+511)/512, 128>>>(batch);                         // launch 11
    k_fc<<<GG, 128>>>(fcW, fcb, gam, bet, oW, ob, out);           // launch 12
}

// round 7
// speedup vs baseline: 1.7838x; 1.2959x over previous
#include <cuda_runtime.h>

#define NN 100000
#define NP 100032
#define EI 800000
#define EE 400000
#define HH 128
#define GG 256
#define N_LAYERS 4
#define NTILES 1563        // NP/64
#define NB_NODE 3125       // 3125*32 = 100000
#define NB_CNT  4816       // covers EI+EE+GG*HH threads
#define PREP_B 98
#define PREP_T 256
#define PREP_NT (PREP_B*PREP_T)

// ---------------- scratch ----------------
__device__ float g_h [NP*HH];
__device__ float g_vp[NP*HH];
__device__ float g_vl[NP*HH];
__device__ float g_Ai[NP*HH];
__device__ float g_Ae[NP*HH];
__device__ float g_wint[EE];
__device__ int   g_degi[NN];   // zeroed by k_fc tail (zero-init on load)
__device__ int   g_dege[NN];
__device__ float g_sif[NP];
__device__ float g_bfi[NP];
__device__ float g_sef[NP];
__device__ float g_bfe[NP];
__device__ int   g_offi[NN+1];
__device__ int   g_offe[NN+1];
__device__ int   g_curi[NN];
__device__ int   g_cure[NN];
__device__ int   g_srci[EI];
__device__ float g_wi[EI];
__device__ int   g_srce[EE];
__device__ float g_we[EE];
__device__ int   g_parti[128];
__device__ int   g_parte[128];
__device__ int   g_cnt1;
__device__ int   g_cnt2;
__device__ float g_pool[GG*HH];

__device__ __forceinline__ float silu_f(float x){ return x / (1.f + __expf(-x)); }
__device__ __forceinline__ unsigned long long dup2(float a){
    unsigned long long r; asm("mov.b64 %0, {%1, %1};" : "=l"(r) : "f"(a)); return r;
}
__device__ __forceinline__ void ffma2(unsigned long long& acc, unsigned long long a, unsigned long long b){
    asm("fma.rn.f32x2 %0, %1, %2, %0;" : "+l"(acc) : "l"(a), "l"(b));
}
__device__ __forceinline__ void pf_l2(const void* p){
    asm volatile("prefetch.global.L2 [%0];" :: "l"(p));
}

// ---------------- 1: node init + degree counts + inter weight + pool zero + counter reset ----------------
__global__ void k_init(const float* __restrict__ x, const float* __restrict__ W,
                       const float* __restrict__ b,
                       const int* __restrict__ ei, const int* __restrict__ ee,
                       const float* __restrict__ pos){
    int blk = blockIdx.x;
    if (blk == 0 && threadIdx.x == 0){ g_cnt1 = 0; g_cnt2 = 0; }
    if (blk < NB_NODE){
        __shared__ float Ws[35*HH];
        __shared__ float xs[32*35];
        int t = threadIdx.x;           // 256
        int n0 = blk*32;
        for (int i = t; i < 35*HH; i += 256) Ws[i] = W[i];
        for (int i = t; i < 32*35; i += 256){
            int node = i/35, k = i - node*35;
            xs[i] = x[(n0+node)*35 + k];
        }
        __syncthreads();
        int c = t & 127;
        int g = t >> 7;                // 0/1
        float bb = b[c];
        for (int idx = 0; idx < 16; idx++){
            int node = g*16 + idx;
            float acc = bb;
            #pragma unroll
            for (int k = 0; k < 35; k++) acc += xs[node*35+k]*Ws[k*HH+c];
            g_h[(n0+node)*HH + c] = silu_f(acc);
        }
        float4 z = make_float4(0.f,0.f,0.f,0.f);
        int base4 = n0*32;
        for (int i = t; i < 32*32; i += 256){
            ((float4*)g_vp)[base4+i] = z;
            ((float4*)g_vl)[base4+i] = z;
        }
    } else {
        int t = (blk - NB_NODE)*256 + threadIdx.x;
        if (t < EI){
            atomicAdd(&g_degi[ei[EI+t]], 1);
        } else if (t < EI+EE){
            int e = t - EI;
            int s = ee[e], d = ee[EE+e];
            float dx = pos[s*3+0]-pos[d*3+0];
            float dy = pos[s*3+1]-pos[d*3+1];
            float dz = pos[s*3+2]-pos[d*3+2];
            g_wint[e] = __expf(-(dx*dx+dy*dy+dz*dz));
            atomicAdd(&g_dege[d], 1);
        } else if (t < EI+EE+GG*HH){
            g_pool[t - EI - EE] = 0.f;
        }
    }
}

// ---------------- 2: scan + offsets/cursors/factors + CSR fill (98 co-resident blocks) ----------------
__global__ void __launch_bounds__(PREP_T) k_prep(const int* __restrict__ ei,
                                                 const float* __restrict__ ea,
                                                 const int* __restrict__ ee){
    __shared__ int s[1024];
    __shared__ int spi[128], spe[128];
    int b = blockIdx.x, b0 = b*1024, t = threadIdx.x;

    for (int pass = 0; pass < 2; pass++){
        const int* deg = pass ? g_dege : g_degi;
        int* off  = pass ? g_offe : g_offi;
        int* part = pass ? g_parte : g_parti;
        for (int i = t; i < 1024; i += 256){
            int n = b0 + i; s[i] = (n < NN) ? deg[n] : 0;
        }
        __syncthreads();
        for (int d = 1; d < 1024; d <<= 1){
            int tmp[4];
            #pragma unroll
            for (int j = 0; j < 4; j++){
                int i = t + j*256;
                tmp[j] = (i >= d) ? s[i-d] : 0;
            }
            __syncthreads();
            #pragma unroll
            for (int j = 0; j < 4; j++) s[t + j*256] += tmp[j];
            __syncthreads();
        }
        for (int i = t; i < 1024; i += 256){
            int n = b0 + i; if (n < NN) off[n+1] = s[i];
        }
        if (t == 0) atomicExch(&part[b], s[1023]);
        __syncthreads();
    }
    __threadfence();
    if (t == 0){
        atomicAdd(&g_cnt1, 1);
        int v; do { __nanosleep(128); v = atomicAdd(&g_cnt1, 0); } while (v < PREP_B);
    }
    __syncthreads();

    if (t < 128){
        spi[t] = (t < PREP_B) ? atomicAdd(&g_parti[t], 0) : 0;
        spe[t] = (t < PREP_B) ? atomicAdd(&g_parte[t], 0) : 0;
    }
    __syncthreads();
    for (int d = 1; d < 128; d <<= 1){
        int vi = 0, ve = 0;
        if (t < 128 && t >= d){ vi = spi[t-d]; ve = spe[t-d]; }
        __syncthreads();
        if (t < 128){ spi[t] += vi; spe[t] += ve; }
        __syncthreads();
    }
    int basei = (b > 0) ? spi[b-1] : 0;
    int basee = (b > 0) ? spe[b-1] : 0;

    for (int i = t; i < 1024; i += 256){
        int n = b0 + i;
        if (n >= NN) continue;
        int di = g_degi[n], de = g_dege[n];
        int oi = g_offi[n+1] + basei;
        int oe = g_offe[n+1] + basee;
        g_offi[n+1] = oi;
        g_offe[n+1] = oe;
        g_curi[n] = oi - di;
        g_cure[n] = oe - de;
        if (n == 0){ g_offi[0] = 0; g_offe[0] = 0; }
        float fdi = (float)di, fde = (float)de;
        float inv = 1.f/(fdi+1.f);
        g_sif[n] = inv;
        g_bfi[n] = fdi*inv;
        float L = logf(fde+1.f);
        g_sef[n] = L;
        g_bfe[n] = fde*L;
    }
    __threadfence();
    __syncthreads();
    if (t == 0){
        atomicAdd(&g_cnt2, 1);
        int v; do { __nanosleep(128); v = atomicAdd(&g_cnt2, 0); } while (v < PREP_B);
    }
    __syncthreads();

    for (int e = b*PREP_T + t; e < EI; e += PREP_NT){
        int s_ = ei[e], d = ei[EI+e];
        int p = atomicAdd(&g_curi[d], 1);
        g_srci[p] = s_; g_wi[p] = ea[e];
    }
    for (int e = b*PREP_T + t; e < EE; e += PREP_NT){
        int s_ = ee[e], d = ee[EE+e];
        int p = atomicAdd(&g_cure[d], 1);
        g_srce[p] = s_; g_we[p] = g_wint[e];
    }
}

// ---------------- per layer: gather (warp per dst node, 4x unrolled edges) ----------------
__global__ void __launch_bounds__(256) k_gather(){
    int gw = (blockIdx.x*256 + threadIdx.x) >> 5;
    if (gw >= NN) return;
    int lane = threadIdx.x & 31;
    int c4 = lane*4;

    {
        int a0 = g_offi[gw], a1 = g_offi[gw+1];
        float4 x0 = make_float4(0,0,0,0), x1 = x0, x2 = x0, x3 = x0;
        int j = a0;
        for (; j + 4 <= a1; j += 4){
            int s0 = __ldg(&g_srci[j+0]); float w0 = __ldg(&g_wi[j+0]);
            int s1 = __ldg(&g_srci[j+1]); float w1 = __ldg(&g_wi[j+1]);
            int s2 = __ldg(&g_srci[j+2]); float w2 = __ldg(&g_wi[j+2]);
            int s3 = __ldg(&g_srci[j+3]); float w3 = __ldg(&g_wi[j+3]);
            float4 h0 = *(const float4*)&g_h[s0*HH + c4];
            float4 h1 = *(const float4*)&g_h[s1*HH + c4];
            float4 h2 = *(const float4*)&g_h[s2*HH + c4];
            float4 h3 = *(const float4*)&g_h[s3*HH + c4];
            x0.x += w0*h0.x; x0.y += w0*h0.y; x0.z += w0*h0.z; x0.w += w0*h0.w;
            x1.x += w1*h1.x; x1.y += w1*h1.y; x1.z += w1*h1.z; x1.w += w1*h1.w;
            x2.x += w2*h2.x; x2.y += w2*h2.y; x2.z += w2*h2.z; x2.w += w2*h2.w;
            x3.x += w3*h3.x; x3.y += w3*h3.y; x3.z += w3*h3.z; x3.w += w3*h3.w;
        }
        for (; j < a1; j++){
            int s = __ldg(&g_srci[j]); float w = __ldg(&g_wi[j]);
            float4 hv = *(const float4*)&g_h[s*HH + c4];
            x0.x += w*hv.x; x0.y += w*hv.y; x0.z += w*hv.z; x0.w += w*hv.w;
        }
        float sc = g_sif[gw];
        *(float4*)&g_Ai[gw*HH + c4] = make_float4(
            (x0.x+x1.x+x2.x+x3.x)*sc, (x0.y+x1.y+x2.y+x3.y)*sc,
            (x0.z+x1.z+x2.z+x3.z)*sc, (x0.w+x1.w+x2.w+x3.w)*sc);
    }
    {
        int a0 = g_offe[gw], a1 = g_offe[gw+1];
        float4 x0 = make_float4(0,0,0,0), x1 = x0, x2 = x0, x3 = x0;
        int j = a0;
        for (; j + 4 <= a1; j += 4){
            int s0 = __ldg(&g_srce[j+0]); float w0 = __ldg(&g_we[j+0]);
            int s1 = __ldg(&g_srce[j+1]); float w1 = __ldg(&g_we[j+1]);
            int s2 = __ldg(&g_srce[j+2]); float w2 = __ldg(&g_we[j+2]);
            int s3 = __ldg(&g_srce[j+3]); float w3 = __ldg(&g_we[j+3]);
            float4 h0 = *(const float4*)&g_h[s0*HH + c4];
            float4 h1 = *(const float4*)&g_h[s1*HH + c4];
            float4 h2 = *(const float4*)&g_h[s2*HH + c4];
            float4 h3 = *(const float4*)&g_h[s3*HH + c4];
            x0.x += w0*h0.x; x0.y += w0*h0.y; x0.z += w0*h0.z; x0.w += w0*h0.w;
            x1.x += w1*h1.x; x1.y += w1*h1.y; x1.z += w1*h1.z; x1.w += w1*h1.w;
            x2.x += w2*h2.x; x2.y += w2*h2.y; x2.z += w2*h2.z; x2.w += w2*h2.w;
            x3.x += w3*h3.x; x3.y += w3*h3.y; x3.z += w3*h3.z; x3.w += w3*h3.w;
        }
        for (; j < a1; j++){
            int s = __ldg(&g_srce[j]); float w = __ldg(&g_we[j]);
            float4 hv = *(const float4*)&g_h[s*HH + c4];
            x0.x += w*hv.x; x0.y += w*hv.y; x0.z += w*hv.z; x0.w += w*hv.w;
        }
        float sc = g_sef[gw];
        *(float4*)&g_Ae[gw*HH + c4] = make_float4(
            (x0.x+x1.x+x2.x+x3.x)*sc, (x0.y+x1.y+x2.y+x3.y)*sc,
            (x0.z+x1.z+x2.z+x3.z)*sc, (x0.w+x1.w+x2.w+x3.w)*sc);
    }
}

// ---------------- per layer: dual GEMM + bias + SiLU + state update (512 threads) ----------------
#define AST 132
#define SMEM_LAYER ((128*256 + 2*64*AST)*sizeof(float))   // 198656 B

__global__ void __launch_bounds__(512,1) k_layer(
        const float* __restrict__ Wi, const float* __restrict__ We,
        const float* __restrict__ bi, const float* __restrict__ be)
{
    extern __shared__ float sm[];
    float* ws  = sm;                 // [128][256]: cols 0..127 Wi, 128..255 We
    float* asi = ws  + 128*256;      // [64][AST] A_i tile, reused as sv_p
    float* ase = asi + 64*AST;       // [64][AST] A_e tile, reused as sv_l
    int tid = threadIdx.x;
    int cg = tid & 63, rg = tid >> 6;          // cg: combined col group, rg: row group
    int ccol = cg*4;                           // 0..255
    bool isIntra = (ccol < 128);
    int colb = isIntra ? ccol : (ccol - 128);

    for (int i = tid; i < 8192; i += 512){
        int k = i >> 6;
        int c = (i & 63)*4;
        float4 v = (c < 128) ? *(const float4*)&Wi[k*128 + c]
                             : *(const float4*)&We[k*128 + (c-128)];
        *(float4*)&ws[k*256 + c] = v;
    }
    float4 bvec = isIntra ? *(const float4*)&bi[colb] : *(const float4*)&be[colb];
    const float* bfarr = isIntra ? g_bfi : g_bfe;
    float* gv  = isIntra ? g_vp : g_vl;
    float* svs = isIntra ? asi  : ase;          // epilogue staging buffer (own warp rows only)
    const float* ab_base = (isIntra ? asi : ase) + rg*8*AST;

    for (int tile = blockIdx.x; tile < NTILES; tile += gridDim.x){
        int n0 = tile*64;

        // ---- Phase A: load A tiles into smem (coalesced) ----
        for (int i = tid; i < 2048; i += 512){
            int row = i >> 5, kc = (i & 31)*4;
            int goff = (n0+row)*HH + kc;
            *(float4*)&asi[row*AST + kc] = *(const float4*)&g_Ai[goff];
            *(float4*)&ase[row*AST + kc] = *(const float4*)&g_Ae[goff];
        }
        // ---- L2 prefetch: this tile's vp/vl/h + next tile's A ----
        {
            int nt = tile + gridDim.x;
            int i = tid;
            if (i < 256){                         // 64 rows x 4 segments of 128B
                int row = i >> 2, seg = (i & 3)*32;
                int off = (n0+row)*HH + seg;
                pf_l2(&g_vp[off]); pf_l2(&g_vl[off]); pf_l2(&g_h[off]);
                if (nt < NTILES){
                    int off2 = (nt*64+row)*HH + seg;
                    pf_l2(&g_Ai[off2]); pf_l2(&g_Ae[off2]);
                }
            }
        }
        __syncthreads();

        // ---- Phase B: GEMM (each thread: 8 rows x 4 cols of one matrix) ----
        unsigned long long acc[8][2];
        #pragma unroll
        for (int r = 0; r < 8; r++){ acc[r][0]=0ull; acc[r][1]=0ull; }

        #pragma unroll 2
        for (int k0 = 0; k0 < 128; k0 += 4){
            float4 a4[8];
            #pragma unroll
            for (int r = 0; r < 8; r++) a4[r] = *(const float4*)&ab_base[r*AST + k0];
            #pragma unroll
            for (int kk = 0; kk < 4; kk++){
                ulonglong2 w2 = *(const ulonglong2*)&ws[(k0+kk)*256 + ccol];
                #pragma unroll
                for (int r = 0; r < 8; r++){
                    float a = (kk==0)?a4[r].x:(kk==1)?a4[r].y:(kk==2)?a4[r].z:a4[r].w;
                    unsigned long long aa = dup2(a);
                    ffma2(acc[r][0], aa, w2.x);
                    ffma2(acc[r][1], aa, w2.y);
                }
            }
        }

        // ---- Phase C: epilogue (bias*bf + old state + SiLU) ----
        // Each warp is entirely intra or entirely inter and owns rows rg*8..rg*8+7
        // of its own staging buffer -> lockstep-safe smem reuse, no sync needed.
        #pragma unroll
        for (int r = 0; r < 8; r++){
            int nl = rg*8 + r;
            int n  = n0 + nl;
            float bf = bfarr[n];
            float2 p0 = *(float2*)&acc[r][0];
            float2 p1 = *(float2*)&acc[r][1];
            float4 vo = *(const float4*)&gv[n*HH + colb];
            float4 v;
            v.x = silu_f(p0.x + bvec.x*bf + vo.x);
            v.y = silu_f(p0.y + bvec.y*bf + vo.y);
            v.z = silu_f(p1.x + bvec.z*bf + vo.z);
            v.w = silu_f(p1.y + bvec.w*bf + vo.w);
            *(float4*)&gv[n*HH + colb] = v;
            *(float4*)&svs[nl*AST + colb] = v;
        }
        __syncthreads();

        // ---- Phase D: h += v_p + v_l ----
        for (int i = tid; i < 2048; i += 512){
            int row = i >> 5, kc = (i & 31)*4;
            int goff = (n0+row)*HH + kc;
            float4 hv = *(const float4*)&g_h[goff];
            float4 p  = *(const float4*)&asi[row*AST + kc];
            float4 q  = *(const float4*)&ase[row*AST + kc];
            hv.x += p.x+q.x; hv.y += p.y+q.y; hv.z += p.z+q.z; hv.w += p.w+q.w;
            *(float4*)&g_h[goff] = hv;
        }
        __syncthreads();
    }
}

// ---------------- pooling ----------------
__global__ void k_pool(const int* __restrict__ batch){
    __shared__ int sb[512];
    int c = threadIdx.x;
    int n0 = blockIdx.x*512;
    if (n0 >= NN) return;
    int nend = min(n0+512, NN);
    int cnt = nend - n0;
    for (int i = c; i < cnt; i += 128) sb[i] = batch[n0+i];
    __syncthreads();
    int cur = sb[0];
    float acc = 0.f;
    for (int k = 0; k < cnt; k++){
        int b = sb[k];
        if (b != cur){
            atomicAdd(&g_pool[cur*HH+c], acc);
            acc = 0.f; cur = b;
        }
        acc += g_h[(n0+k)*HH+c];
    }
    atomicAdd(&g_pool[cur*HH+c], acc);
}

// ---------------- FC head (+ degree re-zero for next call) ----------------
__global__ void k_fc(const float* __restrict__ fcW, const float* __restrict__ fcb,
                     const float* __restrict__ gam, const float* __restrict__ bet,
                     const float* __restrict__ oW,  const float* __restrict__ ob,
                     float* __restrict__ out){
    int g = blockIdx.x, c = threadIdx.x;
    __shared__ float s[HH];
    __shared__ float red[HH];
    s[c] = g_pool[g*HH + c];
    for (int i = g*128 + c; i < NN; i += GG*128){ g_degi[i] = 0; g_dege[i] = 0; }
    __syncthreads();
    const float bns = rsqrtf(1.f + 1e-5f);
    for (int j = 0; j < 3; j++){
        const float* W = fcW + j*HH*HH;
        float acc = fcb[j*HH+c];
        #pragma unroll 8
        for (int k = 0; k < HH; k++) acc += s[k]*W[k*HH+c];
        acc = acc > 0.f ? acc : 0.01f*acc;
        acc = acc*bns*gam[j*HH+c] + bet[j*HH+c];
        __syncthreads();
        s[c] = acc;
        __syncthreads();
    }
    red[c] = s[c]*oW[c];
    __syncthreads();
    for (int o = 64; o > 0; o >>= 1){
        if (c < o) red[c] += red[c+o];
        __syncthreads();
    }
    if (c == 0) out[g] = red[0] + ob[0];
}

// ---------------- host ----------------
extern "C" void kernel_launch(void* const* d_in, const int* in_sizes, int n_in,
                              void* d_out, int out_size){
    const float* x    = (const float*)d_in[0];
    const int*   ei   = (const int*)  d_in[1];
    const int*   ee   = (const int*)  d_in[2];
    const float* pos  = (const float*)d_in[3];
    const float* ea   = (const float*)d_in[4];
    const int*   batch= (const int*)  d_in[5];
    const float* lnW  = (const float*)d_in[6];
    const float* lnb  = (const float*)d_in[7];
    const float* Wi   = (const float*)d_in[8];
    const float* bi   = (const float*)d_in[9];
    const float* We   = (const float*)d_in[10];
    const float* be   = (const float*)d_in[11];
    const float* fcW  = (const float*)d_in[12];
    const float* fcb  = (const float*)d_in[13];
    const float* gam  = (const float*)d_in[14];
    const float* bet  = (const float*)d_in[15];
    const float* oW   = (const float*)d_in[16];
    const float* ob   = (const float*)d_in[17];
    float* out = (float*)d_out;

    cudaFuncSetAttribute(k_layer, cudaFuncAttributeMaxDynamicSharedMemorySize, (int)SMEM_LAYER);

    k_init<<<NB_NODE + NB_CNT, 256>>>(x, lnW, lnb, ei, ee, pos);  // launch 1
    k_prep<<<PREP_B, PREP_T>>>(ei, ea, ee);                       // launch 2

    for (int l = 0; l < N_LAYERS; l++){
        k_gather<<<(NN*32+255)/256, 256>>>();                     // launch 3,5,7,9
        k_layer<<<148, 512, SMEM_LAYER>>>(Wi + l*HH*HH, We + l*HH*HH,
                                          bi + l*HH,    be + l*HH); // launch 4 (ncu capture),6,8,10
    }

    k_pool<<<(NN+511)/512, 128>>>(batch);                         // launch 11
    k_fc<<<GG, 128>>>(fcW, fcb, gam, bet, oW, ob, out);           // launch 12
}

// round 8
// speedup vs baseline: 1.8409x; 1.0320x over previous
#include <cuda_runtime.h>

#define NN 100000
#define NP 100032
#define EI 800000
#define EE 400000
#define HH 128
#define GG 256
#define N_LAYERS 4
#define NB_NODE 3125       // 3125*32 = 100000
#define NB_CNT  4816
#define PREP_B 98
#define PREP_T 256
#define PREP_NT (PREP_B*PREP_T)

// k_layer tiling
#define TM32 32
#define NT32 3126          // NP/32
#define AST 132
#define SM_W  0
#define SM_B0 32768
#define SM_B1 (32768 + 8448)          // 8448 = 2*32*AST
#define SM_ST (32768 + 2*8448)
#define SMEM_LAYER ((32768 + 2*8448 + 4096)*sizeof(float))   // 215040 B

// ---------------- scratch ----------------
__device__ float g_h [NP*HH];
__device__ float g_vp[NP*HH];
__device__ float g_vl[NP*HH];
__device__ float g_Ai[NP*HH];
__device__ float g_Ae[NP*HH];
__device__ float g_wint[EE];
__device__ int   g_degi[NN];
__device__ int   g_dege[NN];
__device__ float g_sif[NP];
__device__ float g_bfi[NP];
__device__ float g_sef[NP];
__device__ float g_bfe[NP];
__device__ int   g_offi[NN+1];
__device__ int   g_offe[NN+1];
__device__ int   g_curi[NN];
__device__ int   g_cure[NN];
__device__ int   g_srci[EI];
__device__ float g_wi[EI];
__device__ int   g_srce[EE];
__device__ float g_we[EE];
__device__ int   g_parti[128];
__device__ int   g_parte[128];
__device__ int   g_cnt1;
__device__ int   g_cnt2;
__device__ float g_pool[GG*HH];

__device__ __forceinline__ float silu_f(float x){ return x / (1.f + __expf(-x)); }
__device__ __forceinline__ unsigned long long dup2(float a){
    unsigned long long r; asm("mov.b64 %0, {%1, %1};" : "=l"(r) : "f"(a)); return r;
}
__device__ __forceinline__ void ffma2(unsigned long long& acc, unsigned long long a, unsigned long long b){
    asm("fma.rn.f32x2 %0, %1, %2, %0;" : "+l"(acc) : "l"(a), "l"(b));
}
__device__ __forceinline__ void pf_l2(const void* p){
    asm volatile("prefetch.global.L2 [%0];" :: "l"(p));
}
__device__ __forceinline__ void cp16(unsigned dst, const void* src){
    asm volatile("cp.async.cg.shared.global [%0], [%1], 16;" :: "r"(dst), "l"(src));
}
__device__ __forceinline__ void cp_commit(){
    asm volatile("cp.async.commit_group;" ::: "memory");
}
__device__ __forceinline__ void cp_wait1(){
    asm volatile("cp.async.wait_group 1;" ::: "memory");
}

// ---------------- 1: node init + degree counts + inter weight + pool zero ----------------
__global__ void k_init(const float* __restrict__ x, const float* __restrict__ W,
                       const float* __restrict__ b,
                       const int* __restrict__ ei, const int* __restrict__ ee,
                       const float* __restrict__ pos){
    int blk = blockIdx.x;
    if (blk == 0 && threadIdx.x == 0){ g_cnt1 = 0; g_cnt2 = 0; }
    if (blk < NB_NODE){
        __shared__ float Ws[35*HH];
        __shared__ float xs[32*35];
        int t = threadIdx.x;           // 256
        int n0 = blk*32;
        for (int i = t; i < 35*HH; i += 256) Ws[i] = W[i];
        for (int i = t; i < 32*35; i += 256){
            int node = i/35, k = i - node*35;
            xs[i] = x[(n0+node)*35 + k];
        }
        __syncthreads();
        int c = t & 127;
        int g = t >> 7;
        float bb = b[c];
        for (int idx = 0; idx < 16; idx++){
            int node = g*16 + idx;
            float acc = bb;
            #pragma unroll
            for (int k = 0; k < 35; k++) acc += xs[node*35+k]*Ws[k*HH+c];
            g_h[(n0+node)*HH + c] = silu_f(acc);
        }
        float4 z = make_float4(0.f,0.f,0.f,0.f);
        int base4 = n0*32;
        for (int i = t; i < 32*32; i += 256){
            ((float4*)g_vp)[base4+i] = z;
            ((float4*)g_vl)[base4+i] = z;
        }
    } else {
        int t = (blk - NB_NODE)*256 + threadIdx.x;
        if (t < EI){
            atomicAdd(&g_degi[ei[EI+t]], 1);
        } else if (t < EI+EE){
            int e = t - EI;
            int s = ee[e], d = ee[EE+e];
            float dx = pos[s*3+0]-pos[d*3+0];
            float dy = pos[s*3+1]-pos[d*3+1];
            float dz = pos[s*3+2]-pos[d*3+2];
            g_wint[e] = __expf(-(dx*dx+dy*dy+dz*dz));
            atomicAdd(&g_dege[d], 1);
        } else if (t < EI+EE+GG*HH){
            g_pool[t - EI - EE] = 0.f;
        }
    }
}

// ---------------- 2: scan + offsets/cursors/factors + CSR fill ----------------
__global__ void __launch_bounds__(PREP_T) k_prep(const int* __restrict__ ei,
                                                 const float* __restrict__ ea,
                                                 const int* __restrict__ ee){
    __shared__ int s[1024];
    __shared__ int spi[128], spe[128];
    int b = blockIdx.x, b0 = b*1024, t = threadIdx.x;

    for (int pass = 0; pass < 2; pass++){
        const int* deg = pass ? g_dege : g_degi;
        int* off  = pass ? g_offe : g_offi;
        int* part = pass ? g_parte : g_parti;
        for (int i = t; i < 1024; i += 256){
            int n = b0 + i; s[i] = (n < NN) ? deg[n] : 0;
        }
        __syncthreads();
        for (int d = 1; d < 1024; d <<= 1){
            int tmp[4];
            #pragma unroll
            for (int j = 0; j < 4; j++){
                int i = t + j*256;
                tmp[j] = (i >= d) ? s[i-d] : 0;
            }
            __syncthreads();
            #pragma unroll
            for (int j = 0; j < 4; j++) s[t + j*256] += tmp[j];
            __syncthreads();
        }
        for (int i = t; i < 1024; i += 256){
            int n = b0 + i; if (n < NN) off[n+1] = s[i];
        }
        if (t == 0) atomicExch(&part[b], s[1023]);
        __syncthreads();
    }
    __threadfence();
    if (t == 0){
        atomicAdd(&g_cnt1, 1);
        int v; do { __nanosleep(128); v = atomicAdd(&g_cnt1, 0); } while (v < PREP_B);
    }
    __syncthreads();

    if (t < 128){
        spi[t] = (t < PREP_B) ? atomicAdd(&g_parti[t], 0) : 0;
        spe[t] = (t < PREP_B) ? atomicAdd(&g_parte[t], 0) : 0;
    }
    __syncthreads();
    for (int d = 1; d < 128; d <<= 1){
        int vi = 0, ve = 0;
        if (t < 128 && t >= d){ vi = spi[t-d]; ve = spe[t-d]; }
        __syncthreads();
        if (t < 128){ spi[t] += vi; spe[t] += ve; }
        __syncthreads();
    }
    int basei = (b > 0) ? spi[b-1] : 0;
    int basee = (b > 0) ? spe[b-1] : 0;

    for (int i = t; i < 1024; i += 256){
        int n = b0 + i;
        if (n >= NN) continue;
        int di = g_degi[n], de = g_dege[n];
        int oi = g_offi[n+1] + basei;
        int oe = g_offe[n+1] + basee;
        g_offi[n+1] = oi;
        g_offe[n+1] = oe;
        g_curi[n] = oi - di;
        g_cure[n] = oe - de;
        if (n == 0){ g_offi[0] = 0; g_offe[0] = 0; }
        float fdi = (float)di, fde = (float)de;
        float inv = 1.f/(fdi+1.f);
        g_sif[n] = inv;
        g_bfi[n] = fdi*inv;
        float L = logf(fde+1.f);
        g_sef[n] = L;
        g_bfe[n] = fde*L;
    }
    __threadfence();
    __syncthreads();
    if (t == 0){
        atomicAdd(&g_cnt2, 1);
        int v; do { __nanosleep(128); v = atomicAdd(&g_cnt2, 0); } while (v < PREP_B);
    }
    __syncthreads();

    for (int e = b*PREP_T + t; e < EI; e += PREP_NT){
        int s_ = ei[e], d = ei[EI+e];
        int p = atomicAdd(&g_curi[d], 1);
        g_srci[p] = s_; g_wi[p] = ea[e];
    }
    for (int e = b*PREP_T + t; e < EE; e += PREP_NT){
        int s_ = ee[e], d = ee[EE+e];
        int p = atomicAdd(&g_cure[d], 1);
        g_srce[p] = s_; g_we[p] = g_wint[e];
    }
}

// ---------------- per layer: gather (warp per dst node, 4x unrolled) ----------------
__global__ void __launch_bounds__(256) k_gather(){
    int gw = (blockIdx.x*256 + threadIdx.x) >> 5;
    if (gw >= NN) return;
    int lane = threadIdx.x & 31;
    int c4 = lane*4;

    {
        int a0 = g_offi[gw], a1 = g_offi[gw+1];
        float4 x0 = make_float4(0,0,0,0), x1 = x0, x2 = x0, x3 = x0;
        int j = a0;
        for (; j + 4 <= a1; j += 4){
            int s0 = __ldg(&g_srci[j+0]); float w0 = __ldg(&g_wi[j+0]);
            int s1 = __ldg(&g_srci[j+1]); float w1 = __ldg(&g_wi[j+1]);
            int s2 = __ldg(&g_srci[j+2]); float w2 = __ldg(&g_wi[j+2]);
            int s3 = __ldg(&g_srci[j+3]); float w3 = __ldg(&g_wi[j+3]);
            float4 h0 = *(const float4*)&g_h[s0*HH + c4];
            float4 h1 = *(const float4*)&g_h[s1*HH + c4];
            float4 h2 = *(const float4*)&g_h[s2*HH + c4];
            float4 h3 = *(const float4*)&g_h[s3*HH + c4];
            x0.x += w0*h0.x; x0.y += w0*h0.y; x0.z += w0*h0.z; x0.w += w0*h0.w;
            x1.x += w1*h1.x; x1.y += w1*h1.y; x1.z += w1*h1.z; x1.w += w1*h1.w;
            x2.x += w2*h2.x; x2.y += w2*h2.y; x2.z += w2*h2.z; x2.w += w2*h2.w;
            x3.x += w3*h3.x; x3.y += w3*h3.y; x3.z += w3*h3.z; x3.w += w3*h3.w;
        }
        for (; j < a1; j++){
            int s = __ldg(&g_srci[j]); float w = __ldg(&g_wi[j]);
            float4 hv = *(const float4*)&g_h[s*HH + c4];
            x0.x += w*hv.x; x0.y += w*hv.y; x0.z += w*hv.z; x0.w += w*hv.w;
        }
        float sc = g_sif[gw];
        *(float4*)&g_Ai[gw*HH + c4] = make_float4(
            (x0.x+x1.x+x2.x+x3.x)*sc, (x0.y+x1.y+x2.y+x3.y)*sc,
            (x0.z+x1.z+x2.z+x3.z)*sc, (x0.w+x1.w+x2.w+x3.w)*sc);
    }
    {
        int a0 = g_offe[gw], a1 = g_offe[gw+1];
        float4 x0 = make_float4(0,0,0,0), x1 = x0, x2 = x0, x3 = x0;
        int j = a0;
        for (; j + 4 <= a1; j += 4){
            int s0 = __ldg(&g_srce[j+0]); float w0 = __ldg(&g_we[j+0]);
            int s1 = __ldg(&g_srce[j+1]); float w1 = __ldg(&g_we[j+1]);
            int s2 = __ldg(&g_srce[j+2]); float w2 = __ldg(&g_we[j+2]);
            int s3 = __ldg(&g_srce[j+3]); float w3 = __ldg(&g_we[j+3]);
            float4 h0 = *(const float4*)&g_h[s0*HH + c4];
            float4 h1 = *(const float4*)&g_h[s1*HH + c4];
            float4 h2 = *(const float4*)&g_h[s2*HH + c4];
            float4 h3 = *(const float4*)&g_h[s3*HH + c4];
            x0.x += w0*h0.x; x0.y += w0*h0.y; x0.z += w0*h0.z; x0.w += w0*h0.w;
            x1.x += w1*h1.x; x1.y += w1*h1.y; x1.z += w1*h1.z; x1.w += w1*h1.w;
            x2.x += w2*h2.x; x2.y += w2*h2.y; x2.z += w2*h2.z; x2.w += w2*h2.w;
            x3.x += w3*h3.x; x3.y += w3*h3.y; x3.z += w3*h3.z; x3.w += w3*h3.w;
        }
        for (; j < a1; j++){
            int s = __ldg(&g_srce[j]); float w = __ldg(&g_we[j]);
            float4 hv = *(const float4*)&g_h[s*HH + c4];
            x0.x += w*hv.x; x0.y += w*hv.y; x0.z += w*hv.z; x0.w += w*hv.w;
        }
        float sc = g_sef[gw];
        *(float4*)&g_Ae[gw*HH + c4] = make_float4(
            (x0.x+x1.x+x2.x+x3.x)*sc, (x0.y+x1.y+x2.y+x3.y)*sc,
            (x0.z+x1.z+x2.z+x3.z)*sc, (x0.w+x1.w+x2.w+x3.w)*sc);
    }
}

// ---------------- issue one tile's A/Ae async load into smem buffer ----------------
__device__ __forceinline__ void issue_tile(unsigned smbase, int tile, int buf, int tid){
    int base = tile*TM32;
    unsigned boff = (buf ? SM_B1 : SM_B0);
    #pragma unroll
    for (int c = tid; c < 1024; c += 512){
        int row = c >> 5, seg = (c & 31)*4;
        unsigned dA = smbase + (boff + row*AST + seg)*4u;
        cp16(dA, &g_Ai[(base+row)*HH + seg]);
        unsigned dE = smbase + (boff + TM32*AST + row*AST + seg)*4u;
        cp16(dE, &g_Ae[(base+row)*HH + seg]);
    }
}

// ---------------- per layer: pipelined dual GEMM + SiLU + state + h update ----------------
__global__ void __launch_bounds__(512,1) k_layer(
        const float* __restrict__ Wi, const float* __restrict__ We,
        const float* __restrict__ bi, const float* __restrict__ be)
{
    extern __shared__ float sm[];
    float* ws = sm;                        // [128][256]
    int tid = threadIdx.x;
    int cg = tid & 63, rg = tid >> 6;      // rg: 8 row groups x 4 rows
    int ccol = cg*4;
    bool isIntra = (ccol < 128);
    int colb = isIntra ? ccol : (ccol - 128);
    unsigned smbase = (unsigned)__cvta_generic_to_shared(sm);

    // prologue: start async load of first tile into buf0 (overlaps W load)
    int tile0 = blockIdx.x;
    issue_tile(smbase, tile0, 0, tid);
    cp_commit();

    for (int i = tid; i < 8192; i += 512){
        int k = i >> 6;
        int c = (i & 63)*4;
        float4 v = (c < 128) ? *(const float4*)&Wi[k*128 + c]
                             : *(const float4*)&We[k*128 + (c-128)];
        *(float4*)&ws[k*256 + c] = v;
    }
    float4 bvec = isIntra ? *(const float4*)&bi[colb] : *(const float4*)&be[colb];
    const float* bfarr = isIntra ? g_bfi : g_bfe;
    float* gv = isIntra ? g_vp : g_vl;

    int buf = 0;
    for (int tile = tile0; tile < NT32; tile += gridDim.x, buf ^= 1){
        int n0 = tile*TM32;
        int nxt = tile + gridDim.x;
        if (nxt < NT32) issue_tile(smbase, nxt, buf^1, tid);
        cp_commit();

        // register-prefetch old state + bf; L2-prefetch h tile
        float4 vo[4]; float bfv[4];
        #pragma unroll
        for (int r = 0; r < 4; r++){
            int n = n0 + rg*4 + r;
            vo[r] = *(const float4*)&gv[n*HH + colb];
            bfv[r] = bfarr[n];
        }
        if (tid < 128){
            int row = tid >> 2, seg = (tid & 3)*32;
            pf_l2(&g_h[(n0+row)*HH + seg]);
        }

        cp_wait1();
        __syncthreads();

        const float* bufp = sm + (buf ? SM_B1 : SM_B0);
        const float* ab = (isIntra ? bufp : bufp + TM32*AST) + rg*4*AST;

        unsigned long long acc[4][2];
        #pragma unroll
        for (int r = 0; r < 4; r++){ acc[r][0]=0ull; acc[r][1]=0ull; }

        #pragma unroll 2
        for (int k0 = 0; k0 < 128; k0 += 4){
            float4 a4[4];
            #pragma unroll
            for (int r = 0; r < 4; r++) a4[r] = *(const float4*)&ab[r*AST + k0];
            #pragma unroll
            for (int kk = 0; kk < 4; kk++){
                ulonglong2 w2 = *(const ulonglong2*)&ws[(k0+kk)*256 + ccol];
                #pragma unroll
                for (int r = 0; r < 4; r++){
                    float a = (kk==0)?a4[r].x:(kk==1)?a4[r].y:(kk==2)?a4[r].z:a4[r].w;
                    unsigned long long aa = dup2(a);
                    ffma2(acc[r][0], aa, w2.x);
                    ffma2(acc[r][1], aa, w2.y);
                }
            }
        }

        // epilogue: v = silu(m + b*bf + v_old); write state; inter stages v_l in smem
        float4 vv[4];
        #pragma unroll
        for (int r = 0; r < 4; r++){
            int n = n0 + rg*4 + r;
            float2 p0 = *(float2*)&acc[r][0];
            float2 p1 = *(float2*)&acc[r][1];
            float bf = bfv[r];
            float4 v;
            v.x = silu_f(p0.x + bvec.x*bf + vo[r].x);
            v.y = silu_f(p0.y + bvec.y*bf + vo[r].y);
            v.z = silu_f(p1.x + bvec.z*bf + vo[r].z);
            v.w = silu_f(p1.y + bvec.w*bf + vo[r].w);
            *(float4*)&gv[n*HH + colb] = v;
            vv[r] = v;
            if (!isIntra) *(float4*)&sm[SM_ST + (rg*4+r)*128 + colb] = v;
        }
        __syncthreads();

        // intra threads finish: h += v_p + v_l
        if (isIntra){
            #pragma unroll
            for (int r = 0; r < 4; r++){
                int n = n0 + rg*4 + r;
                float4 hv = *(const float4*)&g_h[n*HH + colb];
                float4 u  = *(const float4*)&sm[SM_ST + (rg*4+r)*128 + colb];
                hv.x += vv[r].x + u.x;
                hv.y += vv[r].y + u.y;
                hv.z += vv[r].z + u.z;
                hv.w += vv[r].w + u.w;
                *(float4*)&g_h[n*HH + colb] = hv;
            }
        }
    }
}

// ---------------- pooling ----------------
__global__ void k_pool(const int* __restrict__ batch){
    __shared__ int sb[512];
    int c = threadIdx.x;
    int n0 = blockIdx.x*512;
    if (n0 >= NN) return;
    int nend = min(n0+512, NN);
    int cnt = nend - n0;
    for (int i = c; i < cnt; i += 128) sb[i] = batch[n0+i];
    __syncthreads();
    int cur = sb[0];
    float acc = 0.f;
    for (int k = 0; k < cnt; k++){
        int b = sb[k];
        if (b != cur){
            atomicAdd(&g_pool[cur*HH+c], acc);
            acc = 0.f; cur = b;
        }
        acc += g_h[(n0+k)*HH+c];
    }
    atomicAdd(&g_pool[cur*HH+c], acc);
}

// ---------------- FC head (+ degree re-zero) ----------------
__global__ void k_fc(const float* __restrict__ fcW, const float* __restrict__ fcb,
                     const float* __restrict__ gam, const float* __restrict__ bet,
                     const float* __restrict__ oW,  const float* __restrict__ ob,
                     float* __restrict__ out){
    int g = blockIdx.x, c = threadIdx.x;
    __shared__ float s[HH];
    __shared__ float red[HH];
    s[c] = g_pool[g*HH + c];
    for (int i = g*128 + c; i < NN; i += GG*128){ g_degi[i] = 0; g_dege[i] = 0; }
    __syncthreads();
    const float bns = rsqrtf(1.f + 1e-5f);
    for (int j = 0; j < 3; j++){
        const float* W = fcW + j*HH*HH;
        float acc = fcb[j*HH+c];
        #pragma unroll 8
        for (int k = 0; k < HH; k++) acc += s[k]*W[k*HH+c];
        acc = acc > 0.f ? acc : 0.01f*acc;
        acc = acc*bns*gam[j*HH+c] + bet[j*HH+c];
        __syncthreads();
        s[c] = acc;
        __syncthreads();
    }
    red[c] = s[c]*oW[c];
    __syncthreads();
    for (int o = 64; o > 0; o >>= 1){
        if (c < o) red[c] += red[c+o];
        __syncthreads();
    }
    if (c == 0) out[g] = red[0] + ob[0];
}

// ---------------- host ----------------
extern "C" void kernel_launch(void* const* d_in, const int* in_sizes, int n_in,
                              void* d_out, int out_size){
    const float* x    = (const float*)d_in[0];
    const int*   ei   = (const int*)  d_in[1];
    const int*   ee   = (const int*)  d_in[2];
    const float* pos  = (const float*)d_in[3];
    const float* ea   = (const float*)d_in[4];
    const int*   batch= (const int*)  d_in[5];
    const float* lnW  = (const float*)d_in[6];
    const float* lnb  = (const float*)d_in[7];
    const float* Wi   = (const float*)d_in[8];
    const float* bi   = (const float*)d_in[9];
    const float* We   = (const float*)d_in[10];
    const float* be   = (const float*)d_in[11];
    const float* fcW  = (const float*)d_in[12];
    const float* fcb  = (const float*)d_in[13];
    const float* gam  = (const float*)d_in[14];
    const float* bet  = (const float*)d_in[15];
    const float* oW   = (const float*)d_in[16];
    const float* ob   = (const float*)d_in[17];
    float* out = (float*)d_out;

    cudaFuncSetAttribute(k_layer, cudaFuncAttributeMaxDynamicSharedMemorySize, (int)SMEM_LAYER);

    k_init<<<NB_NODE + NB_CNT, 256>>>(x, lnW, lnb, ei, ee, pos);  // launch 1
    k_prep<<<PREP_B, PREP_T>>>(ei, ea, ee);                       // launch 2

    for (int l = 0; l < N_LAYERS; l++){
        k_gather<<<(NN*32+255)/256, 256>>>();                     // launch 3,5,7,9
        k_layer<<<148, 512, SMEM_LAYER>>>(Wi + l*HH*HH, We + l*HH*HH,
                                          bi + l*HH,    be + l*HH); // launch 4 (ncu capture),6,8,10
    }

    k_pool<<<(NN+511)/512, 128>>>(batch);                         // launch 11
    k_fc<<<GG, 128>>>(fcW, fcb, gam, bet, oW, ob, out);           // launch 12
}